// round 8
// baseline (speedup 1.0000x reference)
#include <cuda_runtime.h>
#include <float.h>

#define VOCAB 8000
#define C 256
#define P 8
#define BB 16
#define LL 2048
#define T 32                  // positions per block tile
#define ROWS (T + 2*P)        // 48 window-row token ids
#define THREADS 256
#define POS_PER 16            // positions per 128-thread subgroup

__device__ __forceinline__ float2 fmul2(float2 a, float2 b) {
    float2 r;
    asm("mul.rn.f32x2 %0, %1, %2;"
        : "=l"(reinterpret_cast<unsigned long long&>(r))
        : "l"(reinterpret_cast<unsigned long long&>(a)),
          "l"(reinterpret_cast<unsigned long long&>(b)));
    return r;
}

__global__ void gnn_zero_out(float* out) {
    out[blockIdx.x * blockDim.x + threadIdx.x] = 0.0f;
}

__global__ __launch_bounds__(THREADS, 3)
void gnn_kernel(const int* __restrict__ ids,
                const float* __restrict__ emb,
                const float* __restrict__ ew,
                const float* __restrict__ nw,
                float* __restrict__ out)
{
    __shared__ float2 W_s[T * 16];  // DUPLICATED edge weights {w,w} [pos][j]
    __shared__ float  NN_s[T];      // node weights
    __shared__ int    NX_s[ROWS];   // window-row token ids

    const int b  = blockIdx.y;
    const int l0 = blockIdx.x * T;
    const int* idrow = ids + b * LL;
    const int tid = threadIdx.x;

    // ---- stage token ids ----
    if (tid < ROWS) {
        int p = l0 - P + tid;
        NX_s[tid] = (p >= 0 && p < LL) ? idrow[p] : 0;   // emb row 0 is all-zero
    }
    __syncthreads();

    // ---- edge-weight random DRAM gather, stored duplicated for packed mul ----
    #pragma unroll
    for (int e = tid; e < T * 16; e += THREADS) {
        int t = e >> 4, j = e & 15;
        int k = j + (j >= P);               // window slot, skipping center (8)
        // nx==0 -> emb row 0 all-zero -> product 0 regardless of weight value
        float w = ew[(size_t)NX_s[t + P] * VOCAB + NX_s[t + k]];
        W_s[e] = make_float2(w, w);
    }
    if (tid < T) NN_s[tid] = nw[NX_s[tid + P]];

    // ---- float2 register window init (channels 2ct, 2ct+1), MLP=18 ----
    const int g    = tid >> 7;              // subgroup 0/1
    const int ct   = tid & 127;
    const int base = g * POS_PER;
    const float2* __restrict__ e2 = (const float2*)emb;

    float2 win[17];
    #pragma unroll
    for (int k = 0; k < 17; k++)
        win[k] = e2[(size_t)NX_s[base + k] * (C / 2) + ct];
    float2 nxt = e2[(size_t)NX_s[base + 17] * (C / 2) + ct];
    __syncthreads();

    float acc0 = 0.f, acc1 = 0.f;

    #pragma unroll
    for (int tt = 0; tt < POS_PER; tt++) {
        // depth-2 pipelined prefetch of row base+tt+18
        float2 nxt2 = make_float2(0.f, 0.f);
        if (tt < POS_PER - 2)
            nxt2 = e2[(size_t)NX_s[base + tt + 18] * (C / 2) + ct];

        const float4* wv = (const float4*)(W_s + (base + tt) * 16);
        float nn = NN_s[base + tt];

        // 4 independent max chains, depth 8 each
        float m0a = -FLT_MAX, m0b = -FLT_MAX, m1a = -FLT_MAX, m1b = -FLT_MAX;
        #pragma unroll
        for (int k = 0; k < 8; k++) {
            float4 q = wv[k];                           // {w_j,w_j, w_j1,w_j1}
            const int j0 = 2 * k, j1 = 2 * k + 1;
            float2 v0 = win[(tt + j0 + (j0 >= 8)) % 17];
            float2 v1 = win[(tt + j1 + (j1 >= 8)) % 17];
            float2 p0 = fmul2(v0, make_float2(q.x, q.y));  // MUL2: 2 channels/op
            float2 p1 = fmul2(v1, make_float2(q.z, q.w));
            m0a = fmaxf(m0a, p0.x);  m1a = fmaxf(m1a, p0.y);
            m0b = fmaxf(m0b, p1.x);  m1b = fmaxf(m1b, p1.y);
        }
        float m0 = fmaxf(m0a, m0b);
        float m1 = fmaxf(m1a, m1b);

        float2 rn = win[(tt + 8) % 17];
        acc0 += fmaf(nn, rn.x - m0, m0);   // (1-nn)*m + nn*rn
        acc1 += fmaf(nn, rn.y - m1, m1);

        if (tt < POS_PER - 1) {            // slide (renamed at full unroll)
            win[tt % 17] = nxt;
            nxt = nxt2;
        }
    }

    atomicAdd(&out[b * C + 2 * ct + 0], acc0);
    atomicAdd(&out[b * C + 2 * ct + 1], acc1);
}

extern "C" void kernel_launch(void* const* d_in, const int* in_sizes, int n_in,
                              void* d_out, int out_size) {
    const int*   ids = (const int*)  d_in[0];
    const float* emb = (const float*)d_in[1];
    const float* ew  = (const float*)d_in[2];
    const float* nw  = (const float*)d_in[3];
    float* out = (float*)d_out;

    gnn_zero_out<<<BB, C>>>(out);   // d_out poisoned to 0xAA -> zero first

    dim3 grid(LL / T, BB);
    gnn_kernel<<<grid, THREADS>>>(ids, emb, ew, nw, out);
}

// round 9
// speedup vs baseline: 1.0809x; 1.0809x over previous
#include <cuda_runtime.h>
#include <float.h>

#define VOCAB 8000
#define C 256
#define P 8
#define BB 16
#define LL 2048
#define T 32                   // positions per inner unrolled tile
#define TILES 2
#define TPB (TILES * T)        // 64 positions per block
#define NIDS (TPB + 2 * P)     // 80 window-row ids
#define THREADS 256

__device__ __forceinline__ void cp_async4(void* smem, const void* gptr) {
    unsigned s = (unsigned)__cvta_generic_to_shared(smem);
    asm volatile("cp.async.ca.shared.global [%0], [%1], 4;" :: "r"(s), "l"(gptr));
}

__global__ void gnn_zero_out(float* out) {
    out[blockIdx.x * blockDim.x + threadIdx.x] = 0.0f;
}

__global__ __launch_bounds__(THREADS)
void gnn_kernel(const int* __restrict__ ids,
                const float* __restrict__ emb,
                const float* __restrict__ ew,
                const float* __restrict__ nw,
                float* __restrict__ out)
{
    __shared__ float W_s[TPB * 16];   // edge weights [pos][j]
    __shared__ float NN_s[TPB];       // node weights
    __shared__ int   NX_s[NIDS];      // window-row token ids

    const int b  = blockIdx.y;
    const int l0 = blockIdx.x * TPB;
    const int* idrow = ids + b * LL;
    const int tid = threadIdx.x;
    const int ct  = tid;              // this thread's channel

    // ---- stage token ids for the block's window rows ----
    if (tid < NIDS) {
        int p = l0 - P + tid;
        NX_s[tid] = (p >= 0 && p < LL) ? idrow[p] : 0;   // emb row 0 is all-zero
    }
    __syncthreads();

    // ---- fire-and-forget random gathers via cp.async (no register stall) ----
    #pragma unroll
    for (int e = tid; e < TPB * 16; e += THREADS) {      // 4 per thread
        int t = e >> 4, j = e & 15;
        int k = j + (j >= P);                            // window slot, skip center
        // nx==0 -> emb row 0 all-zero -> product 0 regardless of weight value
        cp_async4(&W_s[e], ew + (size_t)NX_s[t + P] * VOCAB + NX_s[t + k]);
    }
    if (tid < TPB)
        cp_async4(&NN_s[tid], nw + NX_s[tid + P]);
    asm volatile("cp.async.commit_group;" ::: "memory");

    float acc = 0.f;

    #pragma unroll 1
    for (int tile = 0; tile < TILES; tile++) {
        const int base = tile * T;

        // ---- window init: 18 coalesced LDGs (tile 0's overlap the gather) ----
        float win[17];
        #pragma unroll
        for (int k = 0; k < 17; k++)
            win[k] = emb[(size_t)NX_s[base + k] * C + ct];
        float nxt = emb[(size_t)NX_s[base + 17] * C + ct];

        if (tile == 0) {                 // gather landed while init was in flight
            asm volatile("cp.async.wait_group 0;" ::: "memory");
            __syncthreads();
        }

        #pragma unroll
        for (int tt = 0; tt < T; tt++) {
            // depth-2 pipelined prefetch of row base+tt+18
            float nxt2 = 0.f;
            if (tt < T - 2)
                nxt2 = emb[(size_t)NX_s[base + tt + 18] * C + ct];

            const float4* wv = (const float4*)(W_s + (base + tt) * 16);
            float4 wa = wv[0], wb = wv[1], wc = wv[2], wd = wv[3];
            float nn = NN_s[base + tt];

            float m0 = -FLT_MAX, m1 = -FLT_MAX;   // split max chains
            #define STEP(j, wreg, m) m = fmaxf(m, win[(tt + (j) + ((j) >= 8)) % 17] * (wreg));
            STEP(0,  wa.x, m0) STEP(1,  wa.y, m1) STEP(2,  wa.z, m0) STEP(3,  wa.w, m1)
            STEP(4,  wb.x, m0) STEP(5,  wb.y, m1) STEP(6,  wb.z, m0) STEP(7,  wb.w, m1)
            STEP(8,  wc.x, m0) STEP(9,  wc.y, m1) STEP(10, wc.z, m0) STEP(11, wc.w, m1)
            STEP(12, wd.x, m0) STEP(13, wd.y, m1) STEP(14, wd.z, m0) STEP(15, wd.w, m1)
            #undef STEP
            float m = fmaxf(m0, m1);

            float rn = win[(tt + 8) % 17];
            acc += fmaf(nn, rn - m, m);          // (1-nn)*m + nn*rn

            if (tt < T - 1) {                    // slide (register renaming, free)
                win[tt % 17] = nxt;
                nxt = nxt2;
            }
        }
    }

    atomicAdd(&out[b * C + ct], acc);
}

extern "C" void kernel_launch(void* const* d_in, const int* in_sizes, int n_in,
                              void* d_out, int out_size) {
    const int*   ids = (const int*)  d_in[0];
    const float* emb = (const float*)d_in[1];
    const float* ew  = (const float*)d_in[2];
    const float* nw  = (const float*)d_in[3];
    float* out = (float*)d_out;

    gnn_zero_out<<<BB, C>>>(out);   // d_out poisoned to 0xAA -> zero first

    dim3 grid(LL / TPB, BB);
    gnn_kernel<<<grid, THREADS>>>(ids, emb, ew, nw, out);
}

// round 11
// speedup vs baseline: 1.1104x; 1.0273x over previous
#include <cuda_runtime.h>
#include <float.h>

#define VOCAB 8000
#define C 256
#define P 8
#define BB 16
#define LL 2048
#define T 32                  // positions per block tile
#define ROWS (T + 2*P)        // 48 window-row token ids
#define THREADS 256
#define D 5                   // prefetch queue depth (iterations of LDG slack = D+1)

__global__ void gnn_zero_out(float* out) {
    out[blockIdx.x * blockDim.x + threadIdx.x] = 0.0f;
}

__global__ __launch_bounds__(THREADS)
void gnn_kernel(const int* __restrict__ ids,
                const float* __restrict__ emb,
                const float* __restrict__ ew,
                const float* __restrict__ nw,
                float* __restrict__ out)
{
    __shared__ float W_s[T * 16];   // edge weights [pos][j]
    __shared__ float NN_s[T];       // node weights
    __shared__ int   NX_s[ROWS];    // window-row token ids

    const int b  = blockIdx.y;
    const int l0 = blockIdx.x * T;
    const int* idrow = ids + b * LL;
    const int tid = threadIdx.x;
    const int ct  = tid;            // this thread's channel

    // ---- stage token ids for the block's window rows ----
    if (tid < ROWS) {
        int p = l0 - P + tid;
        NX_s[tid] = (p >= 0 && p < LL) ? idrow[p] : 0;   // emb row 0 is all-zero
    }
    __syncthreads();

    // ---- edge-weight random DRAM gather (2 per thread) + node weights ----
    #pragma unroll
    for (int e = tid; e < T * 16; e += THREADS) {
        int t = e >> 4, j = e & 15;
        int k = j + (j >= P);               // window slot, skipping center (8)
        // nx==0 -> emb row 0 all-zero -> product 0 regardless of weight value
        W_s[e] = ew[(size_t)NX_s[t + P] * VOCAB + NX_s[t + k]];
    }
    if (tid < T) NN_s[tid] = nw[NX_s[tid + P]];

    // ---- register window (17) + deep prefetch ring (D), MLP=22 at init ----
    float win[17];
    #pragma unroll
    for (int k = 0; k < 17; k++)
        win[k] = emb[(size_t)NX_s[k] * C + ct];
    float pf[D];
    #pragma unroll
    for (int d = 0; d < D; d++)
        pf[d] = emb[(size_t)NX_s[17 + d] * C + ct];
    __syncthreads();

    float acc = 0.f;

    #pragma unroll
    for (int tt = 0; tt < T; tt++) {
        // LDG issued D+1 iterations before its first read: covers ~262cyc L2 latency
        int r = 17 + D + tt; if (r > ROWS - 1) r = ROWS - 1;   // clamped tail (L1 hits)
        float newv = emb[(size_t)NX_s[r] * C + ct];

        const float4* wv = (const float4*)(W_s + tt * 16);     // broadcast LDS.128
        float4 wa = wv[0], wb = wv[1], wc = wv[2], wd = wv[3];
        float nn = NN_s[tt];

        float m0 = -FLT_MAX, m1 = -FLT_MAX;   // split max chains (depth 8 each)
        #define STEP(j, wreg, m) m = fmaxf(m, win[(tt + (j) + ((j) >= 8)) % 17] * (wreg));
        STEP(0,  wa.x, m0) STEP(1,  wa.y, m1) STEP(2,  wa.z, m0) STEP(3,  wa.w, m1)
        STEP(4,  wb.x, m0) STEP(5,  wb.y, m1) STEP(6,  wb.z, m0) STEP(7,  wb.w, m1)
        STEP(8,  wc.x, m0) STEP(9,  wc.y, m1) STEP(10, wc.z, m0) STEP(11, wc.w, m1)
        STEP(12, wd.x, m0) STEP(13, wd.y, m1) STEP(14, wd.z, m0) STEP(15, wd.w, m1)
        #undef STEP
        float m = fmaxf(m0, m1);

        float rn = win[(tt + 8) % 17];
        acc += fmaf(nn, rn - m, m);           // (1-nn)*m + nn*rn

        // slide through prefetch ring (fully unrolled -> pure register renaming)
        win[tt % 17] = pf[0];
        #pragma unroll
        for (int d = 0; d < D - 1; d++) pf[d] = pf[d + 1];
        pf[D - 1] = newv;
    }

    atomicAdd(&out[b * C + ct], acc);
}

extern "C" void kernel_launch(void* const* d_in, const int* in_sizes, int n_in,
                              void* d_out, int out_size) {
    const int*   ids = (const int*)  d_in[0];
    const float* emb = (const float*)d_in[1];
    const float* ew  = (const float*)d_in[2];
    const float* nw  = (const float*)d_in[3];
    float* out = (float*)d_out;

    gnn_zero_out<<<BB, C>>>(out);   // d_out poisoned to 0xAA -> zero first

    dim3 grid(LL / T, BB);
    gnn_kernel<<<grid, THREADS>>>(ids, emb, ew, nw, out);
}

// round 12
// speedup vs baseline: 1.3053x; 1.1756x over previous
#include <cuda_runtime.h>
#include <float.h>

#define VOCAB 8000
#define C 256
#define P 8
#define BB 16
#define LL 2048
#define T 32                  // positions per block tile
#define ROWS (T + 2*P)        // 48 window-row token ids
#define THREADS 256
#define D 4                   // emb prefetch ring depth

__device__ __forceinline__ void cp_async4(void* smem, const void* gptr) {
    unsigned s = (unsigned)__cvta_generic_to_shared(smem);
    asm volatile("cp.async.ca.shared.global [%0], [%1], 4;" :: "r"(s), "l"(gptr));
}

__global__ void gnn_zero_out(float* out) {
    out[blockIdx.x * blockDim.x + threadIdx.x] = 0.0f;
}

__global__ __launch_bounds__(THREADS)
void gnn_kernel(const int* __restrict__ ids,
                const float* __restrict__ emb,
                const float* __restrict__ ew,
                const float* __restrict__ nw,
                float* __restrict__ out)
{
    __shared__ __align__(16) float W_s[T * 16];   // edge weights [pos][j]
    __shared__ float NN_s[T];                     // node weights
    __shared__ int   NX_s[ROWS];                  // window-row token ids

    const int b  = blockIdx.y;
    const int l0 = blockIdx.x * T;
    const int* idrow = ids + b * LL;
    const int tid = threadIdx.x;
    const int ct  = tid;                          // this thread's channel

    // ---- stage token ids ----
    if (tid < ROWS) {
        int p = l0 - P + tid;
        NX_s[tid] = (p >= 0 && p < LL) ? idrow[p] : 0;   // emb row 0 is all-zero
    }
    __syncthreads();

    // ---- gather group 0: positions 0..15 + all node weights (cp.async, no reg wait)
    {
        int e = tid, t = e >> 4, j = e & 15;
        int k = j + (j >= P);                     // window slot, skipping center
        cp_async4(&W_s[e], ew + (size_t)NX_s[t + P] * VOCAB + NX_s[t + k]);
    }
    if (tid < T)
        cp_async4(&NN_s[tid], nw + NX_s[tid + P]);
    asm volatile("cp.async.commit_group;" ::: "memory");

    // ---- gather group 1: positions 16..31 (overlaps first 16 compute iters)
    {
        int e = tid + THREADS, t = e >> 4, j = e & 15;
        int k = j + (j >= P);
        cp_async4(&W_s[e], ew + (size_t)NX_s[t + P] * VOCAB + NX_s[t + k]);
    }
    asm volatile("cp.async.commit_group;" ::: "memory");

    // ---- register window (17) + prefetch ring (D); overlaps gather group 0 ----
    float win[17];
    #pragma unroll
    for (int k = 0; k < 17; k++)
        win[k] = emb[(size_t)NX_s[k] * C + ct];
    float pf[D];
    #pragma unroll
    for (int d = 0; d < D; d++)
        pf[d] = emb[(size_t)NX_s[17 + d] * C + ct];

    // group 0 (+NN) landed while the 21 window LDGs were in flight
    asm volatile("cp.async.wait_group 1;" ::: "memory");
    __syncthreads();

    float acc = 0.f;
    float4 wa = ((const float4*)W_s)[0];
    float4 wb = ((const float4*)W_s)[1];
    float nn  = NN_s[0];

    #pragma unroll
    for (int tt = 0; tt < T; tt++) {
        if (tt == 16) {                    // second gather half must be visible now
            asm volatile("cp.async.wait_group 0;" ::: "memory");
            __syncthreads();
            wa = ((const float4*)(W_s + 16 * 16))[0];
            wb = ((const float4*)(W_s + 16 * 16))[1];
            nn = NN_s[16];
        }

        // emb prefetch: issued D+1 iters before first read
        int r = 17 + D + tt; if (r > ROWS - 1) r = ROWS - 1;   // clamped tail
        float newv = emb[(size_t)NX_s[r] * C + ct];

        // wc/wd loaded now, consumed >=20 instrs later (LDS latency hidden)
        const float4* wvt = (const float4*)(W_s + tt * 16);
        float4 wc = wvt[2], wd = wvt[3];

        float m0 = win[tt % 17]                 * wa.x;   // j=0 (no max needed)
        float m1 = win[(tt + 1) % 17]           * wa.y;   // j=1
        #define STEP(j, wreg, m) m = fmaxf(m, win[(tt + (j) + ((j) >= 8)) % 17] * (wreg));
        STEP(2,  wa.z, m0) STEP(3,  wa.w, m1)
        STEP(4,  wb.x, m0) STEP(5,  wb.y, m1) STEP(6,  wb.z, m0) STEP(7,  wb.w, m1)
        STEP(8,  wc.x, m0) STEP(9,  wc.y, m1) STEP(10, wc.z, m0) STEP(11, wc.w, m1)
        STEP(12, wd.x, m0) STEP(13, wd.y, m1) STEP(14, wd.z, m0) STEP(15, wd.w, m1)
        #undef STEP
        float m = fmaxf(m0, m1);

        float rn = win[(tt + 8) % 17];
        acc += fmaf(nn, rn - m, m);             // (1-nn)*m + nn*rn

        // prefetch next iteration's wa/wb/nn (skip across the tt==16 barrier)
        if (tt + 1 < T && tt + 1 != 16) {
            const float4* wvn = (const float4*)(W_s + (tt + 1) * 16);
            wa = wvn[0];
            wb = wvn[1];
            nn = NN_s[tt + 1];
        }

        // slide window through prefetch ring (fully unrolled -> register renaming)
        win[tt % 17] = pf[0];
        #pragma unroll
        for (int d = 0; d < D - 1; d++) pf[d] = pf[d + 1];
        pf[D - 1] = newv;
    }

    atomicAdd(&out[b * C + ct], acc);
}

extern "C" void kernel_launch(void* const* d_in, const int* in_sizes, int n_in,
                              void* d_out, int out_size) {
    const int*   ids = (const int*)  d_in[0];
    const float* emb = (const float*)d_in[1];
    const float* ew  = (const float*)d_in[2];
    const float* nw  = (const float*)d_in[3];
    float* out = (float*)d_out;

    gnn_zero_out<<<BB, C>>>(out);   // d_out poisoned to 0xAA -> zero first

    dim3 grid(LL / T, BB);
    gnn_kernel<<<grid, THREADS>>>(ids, emb, ew, nw, out);
}